// round 3
// baseline (speedup 1.0000x reference)
#include <cuda_runtime.h>
#include <math_constants.h>

// Problem constants (fixed shapes for this problem instance)
#define MAXN 100000
#define D 128
#define DOUT 47
#define BN_EPS 1e-5f

// Scratch (device globals; allocation-free per harness rules)
__device__ float g_A[(size_t)MAXN * D];   // GEMM output (h_pre), gathered by src
__device__ float g_B[(size_t)MAXN * D];   // aggregation accumulator
__device__ float g_C[(size_t)MAXN * D];   // h1 (post BN+ReLU), kept for JK max
__device__ float g_deg[MAXN];             // degree -> dinv (in place)
__device__ int   g_is64;                  // edge_index dtype flag (1 = int64, 0 = int32)

// ---------------------------------------------------------------------------
// Edge-index dtype detection + accessor.
// If the array is int64 (little-endian, values < 2^31), every odd 32-bit word
// is 0. For int32 data those words are random node ids -> P(false positive)~0.
// ---------------------------------------------------------------------------
__global__ void detect_dtype(const unsigned int* __restrict__ ei32, int e) {
    if (blockIdx.x == 0 && threadIdx.x == 0) {
        int is64 = 1;
        int lim = (e < 64) ? e : 64;
        for (int i = 0; i < lim; i++) {
            if (ei32[2 * i + 1] != 0u) { is64 = 0; break; }
        }
        g_is64 = is64;
    }
}

// which: 0 = src row, 1 = dst row
__device__ __forceinline__ int load_idx(const void* __restrict__ ei, int e,
                                        int which, int i) {
    if (g_is64) {
        const long long* p = (const long long*)ei;
        return (int)p[(size_t)which * e + i];
    } else {
        const int* p = (const int*)ei;
        return p[(size_t)which * e + i];
    }
}

// ---------------------------------------------------------------------------
// Degree kernels
// ---------------------------------------------------------------------------
__global__ void deg_init(int n) {
    int i = blockIdx.x * blockDim.x + threadIdx.x;
    if (i < n) g_deg[i] = 1.0f;   // self-loop
}

__global__ void deg_count(const void* __restrict__ ei, int e) {
    int i = blockIdx.x * blockDim.x + threadIdx.x;
    if (i < e) {
        int d = load_idx(ei, e, 1, i);
        atomicAdd(&g_deg[d], 1.0f);
    }
}

__global__ void deg_to_dinv(int n) {
    int i = blockIdx.x * blockDim.x + threadIdx.x;
    if (i < n) g_deg[i] = rsqrtf(g_deg[i]);   // deg >= 1 always
}

// ---------------------------------------------------------------------------
// GEMM: out_pre = X @ W  (X: [n,128], W: [128,128])
// Epilogue: g_A = pre ; g_B = pre * dinv[row]^2   (self-loop init of aggregation)
// layer==0: X = x_in param; layer==1: X = g_C
// BM=64, BN=128, BK=32; 256 threads; 8x4 micro-tile per thread.
// ---------------------------------------------------------------------------
#define BM 64
#define BK 32

__global__ __launch_bounds__(256) void gemm128(const float* __restrict__ x_in,
                                               const float* __restrict__ W,
                                               int layer, int n) {
    __shared__ float As[BK][BM + 4];   // transposed x tile, padded
    __shared__ float Bs[BK][D];

    const float* __restrict__ X = (layer == 0) ? x_in : g_C;

    int tid = threadIdx.x;
    int tx = tid & 31;   // column group (4 cols each)
    int ty = tid >> 5;   // row group (8 rows each)
    int blockM = blockIdx.x * BM;

    float acc[8][4];
#pragma unroll
    for (int i = 0; i < 8; i++)
#pragma unroll
        for (int j = 0; j < 4; j++) acc[i][j] = 0.0f;

    for (int k0 = 0; k0 < D; k0 += BK) {
        // Load X tile 64x32 (transposed into As[k][m])
#pragma unroll
        for (int r = 0; r < 2; r++) {
            int i   = tid + 256 * r;      // float4 index, 8 per row
            int row = i >> 3;
            int c4  = i & 7;
            float4 v = make_float4(0.f, 0.f, 0.f, 0.f);
            int gr = blockM + row;
            if (gr < n) v = *(const float4*)&X[(size_t)gr * D + k0 + c4 * 4];
            As[c4 * 4 + 0][row] = v.x;
            As[c4 * 4 + 1][row] = v.y;
            As[c4 * 4 + 2][row] = v.z;
            As[c4 * 4 + 3][row] = v.w;
        }
        // Load W tile 32x128
#pragma unroll
        for (int r = 0; r < 4; r++) {
            int i   = tid + 256 * r;      // float4 index, 32 per row
            int row = i >> 5;
            int c4  = i & 31;
            *(float4*)&Bs[row][c4 * 4] =
                *(const float4*)&W[(size_t)(k0 + row) * D + c4 * 4];
        }
        __syncthreads();

#pragma unroll
        for (int k = 0; k < BK; k++) {
            float a[8];
            *(float4*)&a[0] = *(float4*)&As[k][ty * 8];
            *(float4*)&a[4] = *(float4*)&As[k][ty * 8 + 4];
            float4 b = *(float4*)&Bs[k][tx * 4];
#pragma unroll
            for (int i = 0; i < 8; i++) {
                acc[i][0] += a[i] * b.x;
                acc[i][1] += a[i] * b.y;
                acc[i][2] += a[i] * b.z;
                acc[i][3] += a[i] * b.w;
            }
        }
        __syncthreads();
    }

#pragma unroll
    for (int i = 0; i < 8; i++) {
        int row = blockM + ty * 8 + i;
        if (row < n) {
            float4 v = make_float4(acc[i][0], acc[i][1], acc[i][2], acc[i][3]);
            *(float4*)&g_A[(size_t)row * D + tx * 4] = v;
            float di = g_deg[row];
            float s  = di * di;
            float4 w = make_float4(v.x * s, v.y * s, v.z * s, v.w * s);
            *(float4*)&g_B[(size_t)row * D + tx * 4] = w;
        }
    }
}

// ---------------------------------------------------------------------------
// Edge aggregation: one warp per edge.
// g_B[dst] += g_A[src] * (dinv[src]*dinv[dst])  via red.global.add.v4.f32
// ---------------------------------------------------------------------------
__global__ __launch_bounds__(256) void edge_agg(const void* __restrict__ ei, int e) {
    int idx  = blockIdx.x * blockDim.x + threadIdx.x;
    int eid  = idx >> 5;
    int lane = idx & 31;
    if (eid >= e) return;
    int s = load_idx(ei, e, 0, eid);
    int d = load_idx(ei, e, 1, eid);
    float nrm = g_deg[s] * g_deg[d];
    float4 v = *(const float4*)&g_A[(size_t)s * D + lane * 4];
    float* p = &g_B[(size_t)d * D + lane * 4];
    asm volatile("red.global.add.v4.f32 [%0], {%1, %2, %3, %4};"
                 :: "l"(p), "f"(v.x * nrm), "f"(v.y * nrm),
                    "f"(v.z * nrm), "f"(v.w * nrm)
                 : "memory");
}

// ---------------------------------------------------------------------------
// BN (eval) + ReLU:  g_C = relu(((g_B + b1) - mean) * rsqrt(var+eps) * gamma + beta)
// ---------------------------------------------------------------------------
__global__ __launch_bounds__(256) void bn_relu(const float* __restrict__ b1,
                                               const float* __restrict__ gamma,
                                               const float* __restrict__ beta,
                                               const float* __restrict__ mean,
                                               const float* __restrict__ var,
                                               int n) {
    int total4 = n * (D / 4);
    for (int i = blockIdx.x * blockDim.x + threadIdx.x; i < total4;
         i += gridDim.x * blockDim.x) {
        int c4 = (i & 31) * 4;          // column of the float4
        float4 v  = *(const float4*)&g_B[(size_t)i * 4];
        float4 bb = *(const float4*)&b1[c4];
        float4 mm = *(const float4*)&mean[c4];
        float4 vv = *(const float4*)&var[c4];
        float4 gg = *(const float4*)&gamma[c4];
        float4 be = *(const float4*)&beta[c4];
        float4 r;
        r.x = fmaxf((v.x + bb.x - mm.x) * rsqrtf(vv.x + BN_EPS) * gg.x + be.x, 0.f);
        r.y = fmaxf((v.y + bb.y - mm.y) * rsqrtf(vv.y + BN_EPS) * gg.y + be.y, 0.f);
        r.z = fmaxf((v.z + bb.z - mm.z) * rsqrtf(vv.z + BN_EPS) * gg.z + be.z, 0.f);
        r.w = fmaxf((v.w + bb.w - mm.w) * rsqrtf(vv.w + BN_EPS) * gg.w + be.w, 0.f);
        *(float4*)&g_C[(size_t)i * 4] = r;
    }
}

// ---------------------------------------------------------------------------
// Final: h2 = g_B + b2 ; jk = max(g_C, h2) ; logits = jk @ Wf + bf ; log_softmax
// Warp per node; Wf staged in smem padded to 64 columns (zeros beyond 47).
// ---------------------------------------------------------------------------
__global__ __launch_bounds__(256) void final_kernel(const float* __restrict__ b2,
                                                    const float* __restrict__ Wf,
                                                    const float* __restrict__ bf,
                                                    float* __restrict__ out,
                                                    int n) {
    __shared__ float Wfs[D][64];
    __shared__ float bfs[64];

    for (int i = threadIdx.x; i < D * 64; i += blockDim.x) {
        int r = i >> 6, c = i & 63;
        Wfs[r][c] = (c < DOUT) ? Wf[r * DOUT + c] : 0.0f;
    }
    if (threadIdx.x < 64)
        bfs[threadIdx.x] = (threadIdx.x < DOUT) ? bf[threadIdx.x] : 0.0f;
    __syncthreads();

    int lane = threadIdx.x & 31;
    int wid  = threadIdx.x >> 5;
    int wpb  = blockDim.x >> 5;

    float4 bb = *(const float4*)&b2[lane * 4];

    for (int node = blockIdx.x * wpb + wid; node < n; node += gridDim.x * wpb) {
        float4 h2 = *(const float4*)&g_B[(size_t)node * D + lane * 4];
        float4 h1 = *(const float4*)&g_C[(size_t)node * D + lane * 4];
        float jk[4];
        jk[0] = fmaxf(h1.x, h2.x + bb.x);
        jk[1] = fmaxf(h1.y, h2.y + bb.y);
        jk[2] = fmaxf(h1.z, h2.z + bb.z);
        jk[3] = fmaxf(h1.w, h2.w + bb.w);

        float acc0 = 0.f, acc1 = 0.f;
#pragma unroll
        for (int k = 0; k < D; k++) {
            float v = __shfl_sync(0xFFFFFFFFu, jk[k & 3], k >> 2);
            acc0 += v * Wfs[k][lane];
            acc1 += v * Wfs[k][lane + 32];
        }
        acc0 += bfs[lane];
        acc1 += bfs[lane + 32];

        bool v0 = (lane < DOUT);
        bool v1 = (lane + 32 < DOUT);
        float m = fmaxf(v0 ? acc0 : -CUDART_INF_F, v1 ? acc1 : -CUDART_INF_F);
#pragma unroll
        for (int o = 16; o; o >>= 1) m = fmaxf(m, __shfl_xor_sync(0xFFFFFFFFu, m, o));
        float se = (v0 ? expf(acc0 - m) : 0.f) + (v1 ? expf(acc1 - m) : 0.f);
#pragma unroll
        for (int o = 16; o; o >>= 1) se += __shfl_xor_sync(0xFFFFFFFFu, se, o);
        float lse = m + logf(se);

        if (v0) out[(size_t)node * DOUT + lane] = acc0 - lse;
        if (v1) out[(size_t)node * DOUT + lane + 32] = acc1 - lse;
    }
}

// ---------------------------------------------------------------------------
// Launch
// ---------------------------------------------------------------------------
extern "C" void kernel_launch(void* const* d_in, const int* in_sizes, int n_in,
                              void* d_out, int out_size) {
    const float* x     = (const float*)d_in[0];
    const void*  ei    = d_in[1];
    const float* W1    = (const float*)d_in[2];
    const float* b1    = (const float*)d_in[3];
    const float* gamma = (const float*)d_in[4];
    const float* beta  = (const float*)d_in[5];
    const float* mean  = (const float*)d_in[6];
    const float* var   = (const float*)d_in[7];
    const float* W2    = (const float*)d_in[8];
    const float* b2    = (const float*)d_in[9];
    const float* Wf    = (const float*)d_in[10];
    const float* bf    = (const float*)d_in[11];
    float* out = (float*)d_out;

    int n = in_sizes[0] / D;
    int e = in_sizes[1] / 2;

    // Detect edge_index dtype (int32 vs int64), then degrees -> dinv
    detect_dtype<<<1, 32>>>((const unsigned int*)ei, e);
    deg_init<<<(n + 255) / 256, 256>>>(n);
    deg_count<<<(e + 255) / 256, 256>>>(ei, e);
    deg_to_dinv<<<(n + 255) / 256, 256>>>(n);

    int gemm_grid = (n + BM - 1) / BM;
    int edge_grid = (e * 32 + 255) / 256;   // warp per edge

    // Layer 1
    gemm128<<<gemm_grid, 256>>>(x, W1, 0, n);
    edge_agg<<<edge_grid, 256>>>(ei, e);
    bn_relu<<<2048, 256>>>(b1, gamma, beta, mean, var, n);

    // Layer 2
    gemm128<<<gemm_grid, 256>>>(nullptr, W2, 1, n);
    edge_agg<<<edge_grid, 256>>>(ei, e);

    // JK max + classifier + log_softmax
    final_kernel<<<1480, 256>>>(b2, Wf, bf, out, n);
}

// round 4
// speedup vs baseline: 1.6004x; 1.6004x over previous
#include <cuda_runtime.h>
#include <math_constants.h>

// Problem constants (fixed shapes for this problem instance)
#define MAXN 100000
#define MAXE 1600000
#define D 128
#define DOUT 47
#define BN_EPS 1e-5f

// Scratch (device globals; allocation-free per harness rules)
__device__ float g_A[(size_t)MAXN * D];   // GEMM output, pre-scaled by dinv[row]
__device__ float g_B[(size_t)MAXN * D];   // aggregation output
__device__ float g_C[(size_t)MAXN * D];   // h1 (post BN+ReLU), kept for JK max
__device__ float g_dinv[MAXN];            // 1/sqrt(deg)
__device__ int   g_cnt[MAXN];             // dst histogram (edges only, no self-loop)
__device__ int   g_off[MAXN];             // exclusive prefix of g_cnt
__device__ int   g_cursor[MAXN];          // scatter cursors
__device__ int   g_es[MAXE];              // src ids, sorted by dst
__device__ int   g_bsum[64];              // scan block sums
__device__ int   g_is64;                  // edge_index dtype flag

// ---------------------------------------------------------------------------
// Edge-index dtype detection + accessor (int64 vs silently-downcast int32).
// ---------------------------------------------------------------------------
__global__ void detect_dtype(const unsigned int* __restrict__ ei32, int e) {
    if (blockIdx.x == 0 && threadIdx.x == 0) {
        int is64 = 1;
        int lim = (e < 64) ? e : 64;
        for (int i = 0; i < lim; i++) {
            if (ei32[2 * i + 1] != 0u) { is64 = 0; break; }
        }
        g_is64 = is64;
    }
}

// which: 0 = src row, 1 = dst row
__device__ __forceinline__ int load_idx(const void* __restrict__ ei, int e,
                                        int which, int i) {
    if (g_is64) {
        const long long* p = (const long long*)ei;
        return (int)p[(size_t)which * e + i];
    } else {
        const int* p = (const int*)ei;
        return p[(size_t)which * e + i];
    }
}

// ---------------------------------------------------------------------------
// Counting sort by dst: histogram -> scan -> scatter
// ---------------------------------------------------------------------------
__global__ void cnt_zero(int n) {
    int i = blockIdx.x * blockDim.x + threadIdx.x;
    if (i < n) g_cnt[i] = 0;
}

__global__ void cnt_count(const void* __restrict__ ei, int e) {
    int i = blockIdx.x * blockDim.x + threadIdx.x;
    if (i < e) atomicAdd(&g_cnt[load_idx(ei, e, 1, i)], 1);
}

// Block-level exclusive scan: 256 threads x 8 items = 2048 per block
__global__ __launch_bounds__(256) void scan1(int n) {
    __shared__ int warp_sums[8];
    int tid = threadIdx.x;
    int base = blockIdx.x * 2048 + tid * 8;
    int v[8];
    int tot = 0;
#pragma unroll
    for (int i = 0; i < 8; i++) {
        int idx = base + i;
        v[i] = (idx < n) ? g_cnt[idx] : 0;
        tot += v[i];
    }
    int lane = tid & 31, wid = tid >> 5;
    int x = tot;
#pragma unroll
    for (int o = 1; o < 32; o <<= 1) {
        int y = __shfl_up_sync(0xFFFFFFFFu, x, o);
        if (lane >= o) x += y;
    }
    if (lane == 31) warp_sums[wid] = x;
    __syncthreads();
    if (wid == 0) {
        int w = (lane < 8) ? warp_sums[lane] : 0;
#pragma unroll
        for (int o = 1; o < 8; o <<= 1) {
            int y = __shfl_up_sync(0xFFFFFFFFu, w, o);
            if (lane >= o && lane < 8) w += y;
        }
        if (lane < 8) warp_sums[lane] = w;
    }
    __syncthreads();
    int excl = x - tot + ((wid > 0) ? warp_sums[wid - 1] : 0);
    int run = excl;
#pragma unroll
    for (int i = 0; i < 8; i++) {
        int idx = base + i;
        if (idx < n) g_off[idx] = run;
        run += v[i];
    }
    if (tid == 255) g_bsum[blockIdx.x] = excl + tot;   // block total
}

__global__ void scan2(int nb) {
    if (threadIdx.x == 0 && blockIdx.x == 0) {
        int run = 0;
        for (int i = 0; i < nb; i++) {
            int t = g_bsum[i];
            g_bsum[i] = run;
            run += t;
        }
    }
}

// Add block offsets; also finalize dinv and init scatter cursors.
__global__ void scan3(int n) {
    int i = blockIdx.x * blockDim.x + threadIdx.x;
    if (i < n) {
        int o = g_off[i] + g_bsum[i >> 11];
        g_off[i]    = o;
        g_cursor[i] = o;
        g_dinv[i]   = rsqrtf((float)(g_cnt[i] + 1));   // +1 self-loop
    }
}

__global__ void scatter(const void* __restrict__ ei, int e) {
    int i = blockIdx.x * blockDim.x + threadIdx.x;
    if (i < e) {
        int s = load_idx(ei, e, 0, i);
        int d = load_idx(ei, e, 1, i);
        int p = atomicAdd(&g_cursor[d], 1);
        g_es[p] = s;
    }
}

// ---------------------------------------------------------------------------
// GEMM: g_A = (X @ W) * dinv[row]   (X: [n,128], W: [128,128])
// layer==0: X = x_in. layer==1: X = relu(bn(g_B + b1)) computed inline in the
// A-tile loader, with the BN'd values also written to g_C (needed for JK max).
// BM=64, BN=128, BK=32; 256 threads; 8x4 micro-tile per thread.
// ---------------------------------------------------------------------------
#define BM 64
#define BK 32

__global__ __launch_bounds__(256) void gemm128(const float* __restrict__ x_in,
                                               const float* __restrict__ W,
                                               const float* __restrict__ b1,
                                               const float* __restrict__ gamma,
                                               const float* __restrict__ beta,
                                               const float* __restrict__ mean,
                                               const float* __restrict__ var,
                                               int layer, int n) {
    __shared__ float As[BK][BM + 4];   // transposed x tile, padded
    __shared__ float Bs[BK][D];

    int tid = threadIdx.x;
    int tx = tid & 31;   // column group (4 cols each)
    int ty = tid >> 5;   // row group (8 rows each)
    int blockM = blockIdx.x * BM;

    float acc[8][4];
#pragma unroll
    for (int i = 0; i < 8; i++)
#pragma unroll
        for (int j = 0; j < 4; j++) acc[i][j] = 0.0f;

    for (int k0 = 0; k0 < D; k0 += BK) {
        // Load X tile 64x32 (transposed into As[k][m])
#pragma unroll
        for (int r = 0; r < 2; r++) {
            int i   = tid + 256 * r;      // float4 index, 8 per row
            int row = i >> 3;
            int c4  = i & 7;
            int col = k0 + c4 * 4;
            float4 v = make_float4(0.f, 0.f, 0.f, 0.f);
            int gr = blockM + row;
            if (gr < n) {
                if (layer == 0) {
                    v = *(const float4*)&x_in[(size_t)gr * D + col];
                } else {
                    float4 t  = *(const float4*)&g_B[(size_t)gr * D + col];
                    float4 bb = *(const float4*)&b1[col];
                    float4 mm = *(const float4*)&mean[col];
                    float4 vv = *(const float4*)&var[col];
                    float4 gg = *(const float4*)&gamma[col];
                    float4 be = *(const float4*)&beta[col];
                    v.x = fmaxf((t.x + bb.x - mm.x) * rsqrtf(vv.x + BN_EPS) * gg.x + be.x, 0.f);
                    v.y = fmaxf((t.y + bb.y - mm.y) * rsqrtf(vv.y + BN_EPS) * gg.y + be.y, 0.f);
                    v.z = fmaxf((t.z + bb.z - mm.z) * rsqrtf(vv.z + BN_EPS) * gg.z + be.z, 0.f);
                    v.w = fmaxf((t.w + bb.w - mm.w) * rsqrtf(vv.w + BN_EPS) * gg.w + be.w, 0.f);
                    *(float4*)&g_C[(size_t)gr * D + col] = v;   // h1 for JK max
                }
            }
            As[c4 * 4 + 0][row] = v.x;
            As[c4 * 4 + 1][row] = v.y;
            As[c4 * 4 + 2][row] = v.z;
            As[c4 * 4 + 3][row] = v.w;
        }
        // Load W tile 32x128
#pragma unroll
        for (int r = 0; r < 4; r++) {
            int i   = tid + 256 * r;      // float4 index, 32 per row
            int row = i >> 5;
            int c4  = i & 31;
            *(float4*)&Bs[row][c4 * 4] =
                *(const float4*)&W[(size_t)(k0 + row) * D + c4 * 4];
        }
        __syncthreads();

#pragma unroll
        for (int k = 0; k < BK; k++) {
            float a[8];
            *(float4*)&a[0] = *(float4*)&As[k][ty * 8];
            *(float4*)&a[4] = *(float4*)&As[k][ty * 8 + 4];
            float4 b = *(float4*)&Bs[k][tx * 4];
#pragma unroll
            for (int i = 0; i < 8; i++) {
                acc[i][0] += a[i] * b.x;
                acc[i][1] += a[i] * b.y;
                acc[i][2] += a[i] * b.z;
                acc[i][3] += a[i] * b.w;
            }
        }
        __syncthreads();
    }

#pragma unroll
    for (int i = 0; i < 8; i++) {
        int row = blockM + ty * 8 + i;
        if (row < n) {
            float di = g_dinv[row];
            float4 v = make_float4(acc[i][0] * di, acc[i][1] * di,
                                   acc[i][2] * di, acc[i][3] * di);
            *(float4*)&g_A[(size_t)row * D + tx * 4] = v;
        }
    }
}

// ---------------------------------------------------------------------------
// Segmented aggregation: warp per dst node, NO atomics.
// g_B[d] = (g_A[d] + sum_{s in N(d)} g_A[s]) * dinv[d]
// (g_A rows are pre-scaled by their own dinv; self-loop term is g_A[d]*dinv[d].)
// ---------------------------------------------------------------------------
__global__ __launch_bounds__(256) void agg(int n) {
    int idx  = blockIdx.x * blockDim.x + threadIdx.x;
    int node = idx >> 5;
    int lane = idx & 31;
    if (node >= n) return;

    int beg = g_off[node];
    int cnt = g_cnt[node];

    float4 acc = *(const float4*)&g_A[(size_t)node * D + lane * 4];   // self-loop

    int j = 0;
    for (; j + 2 <= cnt; j += 2) {         // two gathers in flight per warp
        int s0 = g_es[beg + j];
        int s1 = g_es[beg + j + 1];
        float4 v0 = *(const float4*)&g_A[(size_t)s0 * D + lane * 4];
        float4 v1 = *(const float4*)&g_A[(size_t)s1 * D + lane * 4];
        acc.x += v0.x + v1.x;
        acc.y += v0.y + v1.y;
        acc.z += v0.z + v1.z;
        acc.w += v0.w + v1.w;
    }
    if (j < cnt) {
        int s0 = g_es[beg + j];
        float4 v0 = *(const float4*)&g_A[(size_t)s0 * D + lane * 4];
        acc.x += v0.x; acc.y += v0.y; acc.z += v0.z; acc.w += v0.w;
    }

    float di = g_dinv[node];
    float4 r = make_float4(acc.x * di, acc.y * di, acc.z * di, acc.w * di);
    *(float4*)&g_B[(size_t)node * D + lane * 4] = r;
}

// ---------------------------------------------------------------------------
// Final: h2 = g_B + b2 ; jk = max(g_C, h2) ; logits = jk @ Wf + bf ; log_softmax
// Warp per node; Wf staged in smem padded to 64 columns (zeros beyond 47).
// ---------------------------------------------------------------------------
__global__ __launch_bounds__(256) void final_kernel(const float* __restrict__ b2,
                                                    const float* __restrict__ Wf,
                                                    const float* __restrict__ bf,
                                                    float* __restrict__ out,
                                                    int n) {
    __shared__ float Wfs[D][64];
    __shared__ float bfs[64];

    for (int i = threadIdx.x; i < D * 64; i += blockDim.x) {
        int r = i >> 6, c = i & 63;
        Wfs[r][c] = (c < DOUT) ? Wf[r * DOUT + c] : 0.0f;
    }
    if (threadIdx.x < 64)
        bfs[threadIdx.x] = (threadIdx.x < DOUT) ? bf[threadIdx.x] : 0.0f;
    __syncthreads();

    int lane = threadIdx.x & 31;
    int wid  = threadIdx.x >> 5;
    int wpb  = blockDim.x >> 5;

    float4 bb = *(const float4*)&b2[lane * 4];

    for (int node = blockIdx.x * wpb + wid; node < n; node += gridDim.x * wpb) {
        float4 h2 = *(const float4*)&g_B[(size_t)node * D + lane * 4];
        float4 h1 = *(const float4*)&g_C[(size_t)node * D + lane * 4];
        float jk[4];
        jk[0] = fmaxf(h1.x, h2.x + bb.x);
        jk[1] = fmaxf(h1.y, h2.y + bb.y);
        jk[2] = fmaxf(h1.z, h2.z + bb.z);
        jk[3] = fmaxf(h1.w, h2.w + bb.w);

        float acc0 = 0.f, acc1 = 0.f;
#pragma unroll
        for (int k = 0; k < D; k++) {
            float v = __shfl_sync(0xFFFFFFFFu, jk[k & 3], k >> 2);
            acc0 += v * Wfs[k][lane];
            acc1 += v * Wfs[k][lane + 32];
        }
        acc0 += bfs[lane];
        acc1 += bfs[lane + 32];

        bool v0 = (lane < DOUT);
        bool v1 = (lane + 32 < DOUT);
        float m = fmaxf(v0 ? acc0 : -CUDART_INF_F, v1 ? acc1 : -CUDART_INF_F);
#pragma unroll
        for (int o = 16; o; o >>= 1) m = fmaxf(m, __shfl_xor_sync(0xFFFFFFFFu, m, o));
        float se = (v0 ? expf(acc0 - m) : 0.f) + (v1 ? expf(acc1 - m) : 0.f);
#pragma unroll
        for (int o = 16; o; o >>= 1) se += __shfl_xor_sync(0xFFFFFFFFu, se, o);
        float lse = m + logf(se);

        if (v0) out[(size_t)node * DOUT + lane] = acc0 - lse;
        if (v1) out[(size_t)node * DOUT + lane + 32] = acc1 - lse;
    }
}

// ---------------------------------------------------------------------------
// Launch
// ---------------------------------------------------------------------------
extern "C" void kernel_launch(void* const* d_in, const int* in_sizes, int n_in,
                              void* d_out, int out_size) {
    const float* x     = (const float*)d_in[0];
    const void*  ei    = d_in[1];
    const float* W1    = (const float*)d_in[2];
    const float* b1    = (const float*)d_in[3];
    const float* gamma = (const float*)d_in[4];
    const float* beta  = (const float*)d_in[5];
    const float* mean  = (const float*)d_in[6];
    const float* var   = (const float*)d_in[7];
    const float* W2    = (const float*)d_in[8];
    const float* b2    = (const float*)d_in[9];
    const float* Wf    = (const float*)d_in[10];
    const float* bf    = (const float*)d_in[11];
    float* out = (float*)d_out;

    int n = in_sizes[0] / D;
    int e = in_sizes[1] / 2;

    // Dtype detection + counting sort by dst + degrees
    detect_dtype<<<1, 32>>>((const unsigned int*)ei, e);
    cnt_zero<<<(n + 255) / 256, 256>>>(n);
    cnt_count<<<(e + 255) / 256, 256>>>(ei, e);
    int nb = (n + 2047) / 2048;
    scan1<<<nb, 256>>>(n);
    scan2<<<1, 32>>>(nb);
    scan3<<<(n + 255) / 256, 256>>>(n);
    scatter<<<(e + 255) / 256, 256>>>(ei, e);

    int gemm_grid = (n + BM - 1) / BM;
    int agg_grid  = (n * 32 + 255) / 256;   // warp per node

    // Layer 1
    gemm128<<<gemm_grid, 256>>>(x, W1, b1, gamma, beta, mean, var, 0, n);
    agg<<<agg_grid, 256>>>(n);

    // Layer 2 (BN+ReLU fused into A-tile load)
    gemm128<<<gemm_grid, 256>>>(nullptr, W2, b1, gamma, beta, mean, var, 1, n);
    agg<<<agg_grid, 256>>>(n);

    // JK max + classifier + log_softmax
    final_kernel<<<1480, 256>>>(b2, Wf, bf, out, n);
}

// round 6
// speedup vs baseline: 1.7542x; 1.0961x over previous
#include <cuda_runtime.h>
#include <cuda_fp16.h>
#include <math_constants.h>
#include <cstdint>

// Problem constants
#define MAXN 100000
#define MAXE 1600000
#define D 128
#define DOUT 47
#define BN_EPS 1e-5f

// Scratch (device globals; allocation-free per harness rules)
__device__ __half g_A[(size_t)MAXN * D];  // GEMM output (dinv-prescaled), fp16, gathered
__device__ float  g_C[(size_t)MAXN * D];  // h1 (post BN+ReLU), fp32
__device__ float  g_dinv[MAXN];           // 1/sqrt(deg)
__device__ float  g_bn_s[D];              // fused BN scale
__device__ float  g_bn_t[D];              // fused BN bias
__device__ int    g_cnt[MAXN];            // dst histogram (edges only)
__device__ int    g_off[MAXN];            // exclusive prefix of g_cnt
__device__ int    g_cursor[MAXN];         // scatter cursors
__device__ int    g_es[MAXE];             // src ids, sorted by dst
__device__ int    g_bsum[64];             // scan block sums
__device__ int    g_is64;                 // edge_index dtype flag

// ---------------------------------------------------------------------------
// Edge-index dtype detection + accessor (int64 vs silently-downcast int32).
// ---------------------------------------------------------------------------
__global__ void detect_dtype(const unsigned int* __restrict__ ei32, int e) {
    if (blockIdx.x == 0 && threadIdx.x == 0) {
        int is64 = 1;
        int lim = (e < 64) ? e : 64;
        for (int i = 0; i < lim; i++) {
            if (ei32[2 * i + 1] != 0u) { is64 = 0; break; }
        }
        g_is64 = is64;
    }
}

__device__ __forceinline__ int load_idx(const void* __restrict__ ei, int e,
                                        int which, int i) {
    if (g_is64) {
        const long long* p = (const long long*)ei;
        return (int)p[(size_t)which * e + i];
    } else {
        const int* p = (const int*)ei;
        return p[(size_t)which * e + i];
    }
}

// ---------------------------------------------------------------------------
// Counting sort by dst: histogram -> scan -> scatter ; degrees ; BN prep
// ---------------------------------------------------------------------------
__global__ void cnt_zero(int n) {
    int i = blockIdx.x * blockDim.x + threadIdx.x;
    if (i < n) g_cnt[i] = 0;
}

__global__ void cnt_count(const void* __restrict__ ei, int e) {
    int i = blockIdx.x * blockDim.x + threadIdx.x;
    if (i < e) atomicAdd(&g_cnt[load_idx(ei, e, 1, i)], 1);
}

__global__ __launch_bounds__(256) void scan1(int n) {
    __shared__ int warp_sums[8];
    int tid = threadIdx.x;
    int base = blockIdx.x * 2048 + tid * 8;
    int v[8];
    int tot = 0;
#pragma unroll
    for (int i = 0; i < 8; i++) {
        int idx = base + i;
        v[i] = (idx < n) ? g_cnt[idx] : 0;
        tot += v[i];
    }
    int lane = tid & 31, wid = tid >> 5;
    int x = tot;
#pragma unroll
    for (int o = 1; o < 32; o <<= 1) {
        int y = __shfl_up_sync(0xFFFFFFFFu, x, o);
        if (lane >= o) x += y;
    }
    if (lane == 31) warp_sums[wid] = x;
    __syncthreads();
    if (wid == 0) {
        int w = (lane < 8) ? warp_sums[lane] : 0;
#pragma unroll
        for (int o = 1; o < 8; o <<= 1) {
            int y = __shfl_up_sync(0xFFFFFFFFu, w, o);
            if (lane >= o && lane < 8) w += y;
        }
        if (lane < 8) warp_sums[lane] = w;
    }
    __syncthreads();
    int excl = x - tot + ((wid > 0) ? warp_sums[wid - 1] : 0);
    int run = excl;
#pragma unroll
    for (int i = 0; i < 8; i++) {
        int idx = base + i;
        if (idx < n) g_off[idx] = run;
        run += v[i];
    }
    if (tid == 255) g_bsum[blockIdx.x] = excl + tot;
}

__global__ void scan2(int nb) {
    if (threadIdx.x == 0 && blockIdx.x == 0) {
        int run = 0;
        for (int i = 0; i < nb; i++) {
            int t = g_bsum[i];
            g_bsum[i] = run;
            run += t;
        }
    }
}

__global__ void scan3(int n) {
    int i = blockIdx.x * blockDim.x + threadIdx.x;
    if (i < n) {
        int o = g_off[i] + g_bsum[i >> 11];
        g_off[i]    = o;
        g_cursor[i] = o;
        g_dinv[i]   = rsqrtf((float)(g_cnt[i] + 1));   // +1 self-loop
    }
}

__global__ void scatter(const void* __restrict__ ei, int e) {
    int i = blockIdx.x * blockDim.x + threadIdx.x;
    if (i < e) {
        int s = load_idx(ei, e, 0, i);
        int d = load_idx(ei, e, 1, i);
        int p = atomicAdd(&g_cursor[d], 1);
        g_es[p] = s;
    }
}

__global__ void bn_prep(const float* __restrict__ b1, const float* __restrict__ gamma,
                        const float* __restrict__ beta, const float* __restrict__ mean,
                        const float* __restrict__ var) {
    int i = threadIdx.x;
    if (i < D) {
        float rs = rsqrtf(var[i] + BN_EPS);
        float s = rs * gamma[i];
        g_bn_s[i] = s;
        g_bn_t[i] = (b1[i] - mean[i]) * s + beta[i];
    }
}

// ---------------------------------------------------------------------------
// SIMT GEMM: g_A = fp16((X @ W) * dinv[row])   (X: [n,128] fp32, W: [128,128])
// layer==0: X = x_in ; layer==1: X = g_C (BN+ReLU already applied by agg1).
// BM=64, BN=128, BK=32; 256 threads; 8x4 micro-tile per thread.
// ---------------------------------------------------------------------------
#define BM 64
#define BK 32

__global__ __launch_bounds__(256) void gemm128(const float* __restrict__ x_in,
                                               const float* __restrict__ W,
                                               int layer, int n) {
    __shared__ float As[BK][BM + 4];   // transposed x tile, padded
    __shared__ float Bs[BK][D];

    const float* __restrict__ X = (layer == 0) ? x_in : g_C;

    int tid = threadIdx.x;
    int tx = tid & 31;   // column group (4 cols each)
    int ty = tid >> 5;   // row group (8 rows each)
    int blockM = blockIdx.x * BM;

    float acc[8][4];
#pragma unroll
    for (int i = 0; i < 8; i++)
#pragma unroll
        for (int j = 0; j < 4; j++) acc[i][j] = 0.0f;

    for (int k0 = 0; k0 < D; k0 += BK) {
#pragma unroll
        for (int r = 0; r < 2; r++) {
            int i   = tid + 256 * r;      // float4 index, 8 per row
            int row = i >> 3;
            int c4  = i & 7;
            float4 v = make_float4(0.f, 0.f, 0.f, 0.f);
            int gr = blockM + row;
            if (gr < n) v = *(const float4*)&X[(size_t)gr * D + k0 + c4 * 4];
            As[c4 * 4 + 0][row] = v.x;
            As[c4 * 4 + 1][row] = v.y;
            As[c4 * 4 + 2][row] = v.z;
            As[c4 * 4 + 3][row] = v.w;
        }
#pragma unroll
        for (int r = 0; r < 4; r++) {
            int i   = tid + 256 * r;      // float4 index, 32 per row
            int row = i >> 5;
            int c4  = i & 31;
            *(float4*)&Bs[row][c4 * 4] =
                *(const float4*)&W[(size_t)(k0 + row) * D + c4 * 4];
        }
        __syncthreads();

#pragma unroll
        for (int k = 0; k < BK; k++) {
            float a[8];
            *(float4*)&a[0] = *(float4*)&As[k][ty * 8];
            *(float4*)&a[4] = *(float4*)&As[k][ty * 8 + 4];
            float4 b = *(float4*)&Bs[k][tx * 4];
#pragma unroll
            for (int i = 0; i < 8; i++) {
                acc[i][0] += a[i] * b.x;
                acc[i][1] += a[i] * b.y;
                acc[i][2] += a[i] * b.z;
                acc[i][3] += a[i] * b.w;
            }
        }
        __syncthreads();
    }

#pragma unroll
    for (int i = 0; i < 8; i++) {
        int row = blockM + ty * 8 + i;
        if (row < n) {
            float di = g_dinv[row];
            __half2 h0 = __floats2half2_rn(acc[i][0] * di, acc[i][1] * di);
            __half2 h1 = __floats2half2_rn(acc[i][2] * di, acc[i][3] * di);
            uint2 u;
            u.x = *(uint32_t*)&h0;
            u.y = *(uint32_t*)&h1;
            *(uint2*)&g_A[(size_t)row * D + tx * 4] = u;
        }
    }
}

// ---------------------------------------------------------------------------
// Shared gather helper: accumulate fp16 row of g_A into fp32 acc[4].
// Lane l covers cols l*4 .. l*4+3 (8 bytes).
// ---------------------------------------------------------------------------
__device__ __forceinline__ void gather_row(float* acc, int row, int lane) {
    uint2 u = *(const uint2*)&g_A[(size_t)row * D + lane * 4];
    float2 a = __half22float2(*(__half2*)&u.x);
    float2 b = __half22float2(*(__half2*)&u.y);
    acc[0] += a.x; acc[1] += a.y; acc[2] += b.x; acc[3] += b.y;
}

// ---------------------------------------------------------------------------
// agg1: warp per node, no atomics, fused BN+ReLU.
// g_C[d] = relu( bn_s * ((g_A[d] + sum g_A[s]) * dinv[d]) + bn_t )
// ---------------------------------------------------------------------------
__global__ __launch_bounds__(256) void agg1(int n) {
    __shared__ float s_s[D], s_t[D];
    if (threadIdx.x < D) {
        s_s[threadIdx.x] = g_bn_s[threadIdx.x];
        s_t[threadIdx.x] = g_bn_t[threadIdx.x];
    }
    __syncthreads();

    int idx  = blockIdx.x * blockDim.x + threadIdx.x;
    int node = idx >> 5;
    int lane = idx & 31;
    if (node >= n) return;

    int beg = g_off[node];
    int cnt = g_cnt[node];

    float acc[4] = {0.f, 0.f, 0.f, 0.f};
    gather_row(acc, node, lane);   // self-loop

    int j = 0;
    for (; j + 2 <= cnt; j += 2) {
        int s0 = g_es[beg + j];
        int s1 = g_es[beg + j + 1];
        gather_row(acc, s0, lane);
        gather_row(acc, s1, lane);
    }
    if (j < cnt) gather_row(acc, g_es[beg + j], lane);

    float di = g_dinv[node];
    int col = lane * 4;
    float4 r;
    r.x = fmaxf(acc[0] * di * s_s[col]     + s_t[col],     0.f);
    r.y = fmaxf(acc[1] * di * s_s[col + 1] + s_t[col + 1], 0.f);
    r.z = fmaxf(acc[2] * di * s_s[col + 2] + s_t[col + 2], 0.f);
    r.w = fmaxf(acc[3] * di * s_s[col + 3] + s_t[col + 3], 0.f);
    *(float4*)&g_C[(size_t)node * D + col] = r;
}

// ---------------------------------------------------------------------------
// agg2 + final fused: warp per node (grid-stride), no atomics.
// h2 = (g_A[d] + sum g_A[s]) * dinv[d] + b2 ; jk = max(g_C[d], h2)
// logits = jk @ Wf + bf ; out = log_softmax(logits)
// ---------------------------------------------------------------------------
__global__ __launch_bounds__(256) void agg2_final(const float* __restrict__ b2,
                                                  const float* __restrict__ Wf,
                                                  const float* __restrict__ bf,
                                                  float* __restrict__ out,
                                                  int n) {
    __shared__ float Wfs[D][64];
    __shared__ float bfs[64];

    for (int i = threadIdx.x; i < D * 64; i += blockDim.x) {
        int r = i >> 6, c = i & 63;
        Wfs[r][c] = (c < DOUT) ? Wf[r * DOUT + c] : 0.0f;
    }
    if (threadIdx.x < 64)
        bfs[threadIdx.x] = (threadIdx.x < DOUT) ? bf[threadIdx.x] : 0.0f;
    __syncthreads();

    int lane = threadIdx.x & 31;
    int wid  = threadIdx.x >> 5;
    int wpb  = blockDim.x >> 5;

    float4 bb = *(const float4*)&b2[lane * 4];

    for (int node = blockIdx.x * wpb + wid; node < n; node += gridDim.x * wpb) {
        int beg = g_off[node];
        int cnt = g_cnt[node];

        float acc[4] = {0.f, 0.f, 0.f, 0.f};
        gather_row(acc, node, lane);   // self-loop

        int j = 0;
        for (; j + 2 <= cnt; j += 2) {
            int s0 = g_es[beg + j];
            int s1 = g_es[beg + j + 1];
            gather_row(acc, s0, lane);
            gather_row(acc, s1, lane);
        }
        if (j < cnt) gather_row(acc, g_es[beg + j], lane);

        float di = g_dinv[node];
        float4 h1 = *(const float4*)&g_C[(size_t)node * D + lane * 4];
        float jk[4];
        jk[0] = fmaxf(h1.x, acc[0] * di + bb.x);
        jk[1] = fmaxf(h1.y, acc[1] * di + bb.y);
        jk[2] = fmaxf(h1.z, acc[2] * di + bb.z);
        jk[3] = fmaxf(h1.w, acc[3] * di + bb.w);

        float acc0 = 0.f, acc1 = 0.f;
#pragma unroll
        for (int k = 0; k < D; k++) {
            float v = __shfl_sync(0xFFFFFFFFu, jk[k & 3], k >> 2);
            acc0 += v * Wfs[k][lane];
            acc1 += v * Wfs[k][lane + 32];
        }
        acc0 += bfs[lane];
        acc1 += bfs[lane + 32];

        bool v0 = (lane < DOUT);
        bool v1 = (lane + 32 < DOUT);
        float m = fmaxf(v0 ? acc0 : -CUDART_INF_F, v1 ? acc1 : -CUDART_INF_F);
#pragma unroll
        for (int o = 16; o; o >>= 1) m = fmaxf(m, __shfl_xor_sync(0xFFFFFFFFu, m, o));
        float se = (v0 ? expf(acc0 - m) : 0.f) + (v1 ? expf(acc1 - m) : 0.f);
#pragma unroll
        for (int o = 16; o; o >>= 1) se += __shfl_xor_sync(0xFFFFFFFFu, se, o);
        float lse = m + logf(se);

        if (v0) out[(size_t)node * DOUT + lane] = acc0 - lse;
        if (v1) out[(size_t)node * DOUT + lane + 32] = acc1 - lse;
    }
}

// ---------------------------------------------------------------------------
// Launch
// ---------------------------------------------------------------------------
extern "C" void kernel_launch(void* const* d_in, const int* in_sizes, int n_in,
                              void* d_out, int out_size) {
    const float* x     = (const float*)d_in[0];
    const void*  ei    = d_in[1];
    const float* W1    = (const float*)d_in[2];
    const float* b1    = (const float*)d_in[3];
    const float* gamma = (const float*)d_in[4];
    const float* beta  = (const float*)d_in[5];
    const float* mean  = (const float*)d_in[6];
    const float* var   = (const float*)d_in[7];
    const float* W2    = (const float*)d_in[8];
    const float* b2    = (const float*)d_in[9];
    const float* Wf    = (const float*)d_in[10];
    const float* bf    = (const float*)d_in[11];
    float* out = (float*)d_out;

    int n = in_sizes[0] / D;
    int e = in_sizes[1] / 2;

    // Dtype detection + counting sort by dst + degrees + BN prep
    detect_dtype<<<1, 32>>>((const unsigned int*)ei, e);
    cnt_zero<<<(n + 255) / 256, 256>>>(n);
    cnt_count<<<(e + 255) / 256, 256>>>(ei, e);
    int nb = (n + 2047) / 2048;
    scan1<<<nb, 256>>>(n);
    scan2<<<1, 32>>>(nb);
    scan3<<<(n + 255) / 256, 256>>>(n);
    scatter<<<(e + 255) / 256, 256>>>(ei, e);
    bn_prep<<<1, 128>>>(b1, gamma, beta, mean, var);

    int gemm_grid = (n + BM - 1) / BM;
    int agg_grid  = (n * 32 + 255) / 256;   // warp per node, exact

    // Layer 1: GEMM -> aggregation fused with BN+ReLU
    gemm128<<<gemm_grid, 256>>>(x, W1, 0, n);
    agg1<<<agg_grid, 256>>>(n);

    // Layer 2: GEMM -> aggregation fused with JK max + classifier + log_softmax
    gemm128<<<gemm_grid, 256>>>(nullptr, W2, 1, n);
    agg2_final<<<1036, 256>>>(b2, Wf, bf, out, n);
}